// round 6
// baseline (speedup 1.0000x reference)
#include <cuda_runtime.h>
#include <math.h>
#include <stdint.h>

// Problem constants (GraphEmbedderGATNE): N=200000, R=4, D=128, U=32, A=16, E=131072, K=10
#define N_ENT 200000
#define R_ 4
#define D_ 128
#define U_ 32
#define A_ 16
#define E_ 131072
#define K_ 10
#define ES_TOTAL (2 * E_)                 // 262144 edge-sides
#define WPB 22                            // warps per block
#define ES_PER_WARP 4
#define THREADS (WPB * 32)                // 704
#define ES_PER_BLOCK (WPB * ES_PER_WARP)  // 88
#define NBLOCKS ((ES_TOTAL + ES_PER_BLOCK - 1) / ES_PER_BLOCK)  // 2979

// Shared-memory layout (float offsets)
#define SM_M 0                            // M: [(r*32+u)*128 + d], 16384 floats
#define SM_W (SM_M + R_ * U_ * D_)        // W transposed: [r*512 + a*32 + u], 2048 floats
#define SM_w (SM_W + R_ * U_ * A_)        // w: [r*16 + a], 64 floats
#define SM_SCR (SM_w + R_ * A_)           // 18496
// per-warp scratch:
#define QD_OFF 0                          // q duplicated: [b*128 + k][2], 1024 floats (4 es)
#define UR_OFF 1024                       // ur: [r*33 + u] (conflict-free), 132 floats
#define WR_OFF (UR_OFF + 132)             // wr: [u*18 + a] (float2-aligned), 576 floats
#define WARP_FLOATS (WR_OFF + 576)        // 1732 floats / warp (16B-divisible)
#define SMEM_FLOATS (SM_SCR + WPB * WARP_FLOATS)   // 56600
#define SMEM_BYTES (SMEM_FLOATS * 4)      // 226400 bytes (<= 232448 max dynamic)

__device__ __forceinline__ float tanh_fast(float x) {
    float y;
    asm("tanh.approx.f32 %0, %1;" : "=f"(y) : "f"(x));
    return y;
}

// packed fp32x2 FMA: d = a*b + d   (both halves independently)
#define FMA2(d, a, b) \
    asm("fma.rn.f32x2 %0, %1, %2, %3;" : "=l"(d) : "l"(a), "l"(b), "l"(d))

#define PACKF2(out, lo, hi) \
    asm("mov.b64 %0, {%1, %2};" : "=l"(out) : "f"(lo), "f"(hi))

#define UNPACKF2(lo, hi, in) \
    asm("mov.b64 {%0, %1}, %2;" : "=f"(lo), "=f"(hi) : "l"(in))

__global__ void __launch_bounds__(THREADS, 1)
gatne_kernel(const int* __restrict__ edge_index,    // [2, E]
             const float* __restrict__ edge_attr,   // [E, R]
             const int* __restrict__ nidx,          // [2, E, K]
             const float* __restrict__ emb,         // [N, D]
             const float* __restrict__ utab,        // [N, R, U]
             const float* __restrict__ Wt,          // [R, U, A]
             const float* __restrict__ wv,          // [R, A]
             const float* __restrict__ Mt,          // [R, U, D]
             float* __restrict__ out)               // [2, E, D]
{
    extern __shared__ float smem[];
    const int tid = threadIdx.x;

    // --- cooperative loads of the shared weight tables ---
    {
        float4* d = (float4*)(smem + SM_M);
        const float4* s = (const float4*)Mt;
        for (int i = tid; i < (R_ * U_ * D_) / 4; i += THREADS) d[i] = s[i];
    }
    for (int i = tid; i < R_ * U_ * A_; i += THREADS) {
        int r = i >> 9, rem = i & 511, uu = rem >> 4, a = rem & 15;
        smem[SM_W + r * 512 + a * 32 + uu] = Wt[i];
    }
    if (tid < R_ * A_) smem[SM_w + tid] = wv[tid];
    __syncthreads();

    const int warp = tid >> 5, lane = tid & 31;
    float* q_s  = smem + SM_SCR + warp * WARP_FLOATS + QD_OFF;
    float* ur_s = smem + SM_SCR + warp * WARP_FLOATS + UR_OFF;
    float* wr_s = smem + SM_SCR + warp * WARP_FLOATS + WR_OFF;
    const float* W_s = smem + SM_W;
    const float* w_s = smem + SM_w;

    const int es_base = (blockIdx.x * WPB + warp) * ES_PER_WARP;
    const int rg = lane >> 3;          // r-group for the t/score phase
    const int cg = lane & 7;
    const int a0 = 2 * cg;

    // ================= Phase 1: per edge-side attention -> q (duplicated) =====
    #pragma unroll 1
    for (int b = 0; b < ES_PER_WARP; ++b) {
        const int es = es_base + b;
        if (es < ES_TOTAL) {
            const int e = es & (E_ - 1);
            const float4 ea = ((const float4*)edge_attr)[e];

            // neighbor indices: one warp-wide load, distributed by shuffle
            const int* nb = nidx + (long)es * K_;
            int my_n = (lane < K_) ? __ldg(nb + lane) : 0;

            // mean over K neighbors of u rows: lane holds flat (r*32+u) = 4*lane..+3
            float4 au = make_float4(0.f, 0.f, 0.f, 0.f);
            #pragma unroll
            for (int k = 0; k < K_; ++k) {
                int nbr = __shfl_sync(0xffffffffu, my_n, k);
                float4 t = ((const float4*)utab)[(long)nbr * 32 + lane];
                au.x += t.x; au.y += t.y; au.z += t.z; au.w += t.w;
            }
            const float ik = 1.0f / (float)K_;
            au.x *= ik; au.y *= ik; au.z *= ik; au.w *= ik;

            // stash u_r to smem: layout [r*33 + u] (conflict-free)
            const int ub = 4 * cg;  // flat f = 4*lane+j -> r = lane>>3, u = 4*(lane&7)+j
            ur_s[rg * 33 + ub + 0] = au.x;
            ur_s[rg * 33 + ub + 1] = au.y;
            ur_s[rg * 33 + ub + 2] = au.z;
            ur_s[rg * 33 + ub + 3] = au.w;

            // W_r[u=lane][a] = sum_r ea[r] * W[r][u][a]  (W_s transposed [r][a][u])
            #pragma unroll
            for (int a2 = 0; a2 < 8; ++a2) {
                int a = 2 * a2;
                float f0 = fmaf(ea.x, W_s[a * 32 + lane],
                           fmaf(ea.y, W_s[512 + a * 32 + lane],
                           fmaf(ea.z, W_s[1024 + a * 32 + lane],
                                ea.w * W_s[1536 + a * 32 + lane])));
                float f1 = fmaf(ea.x, W_s[(a + 1) * 32 + lane],
                           fmaf(ea.y, W_s[512 + (a + 1) * 32 + lane],
                           fmaf(ea.z, W_s[1024 + (a + 1) * 32 + lane],
                                ea.w * W_s[1536 + (a + 1) * 32 + lane])));
                ((float2*)(wr_s + lane * 18))[a2] = make_float2(f0, f1);
            }
            __syncwarp();

            // t[r=rg][a0], t[r=rg][a0+1] = sum_u u_r[r][u] * W_r[u][a]
            float t0 = 0.f, t1 = 0.f;
            #pragma unroll
            for (int uu = 0; uu < U_; ++uu) {
                float urv = ur_s[rg * 33 + uu];
                float2 w2 = *(const float2*)(wr_s + uu * 18 + a0);
                t0 = fmaf(urv, w2.x, t0);
                t1 = fmaf(urv, w2.y, t1);
            }
            // w_r[a] = ea . w[:, a]
            float wr0 = fmaf(ea.x, w_s[a0], fmaf(ea.y, w_s[16 + a0],
                        fmaf(ea.z, w_s[32 + a0], ea.w * w_s[48 + a0])));
            float wr1 = fmaf(ea.x, w_s[a0 + 1], fmaf(ea.y, w_s[16 + a0 + 1],
                        fmaf(ea.z, w_s[32 + a0 + 1], ea.w * w_s[48 + a0 + 1])));
            float sc = tanh_fast(t0) * wr0 + tanh_fast(t1) * wr1;

            // reduce scores within 8-lane r-group
            sc += __shfl_xor_sync(0xffffffffu, sc, 1);
            sc += __shfl_xor_sync(0xffffffffu, sc, 2);
            sc += __shfl_xor_sync(0xffffffffu, sc, 4);
            // softmax over the 4 r-groups
            float mx = sc;
            mx = fmaxf(mx, __shfl_xor_sync(0xffffffffu, mx, 8));
            mx = fmaxf(mx, __shfl_xor_sync(0xffffffffu, mx, 16));
            float ex = __expf(sc - mx);
            float ssum = ex;
            ssum += __shfl_xor_sync(0xffffffffu, ssum, 8);
            ssum += __shfl_xor_sync(0xffffffffu, ssum, 16);
            float att = __fdividef(ex, ssum);
            float av0 = __shfl_sync(0xffffffffu, att, 0);
            float av1 = __shfl_sync(0xffffffffu, att, 8);
            float av2 = __shfl_sync(0xffffffffu, att, 16);
            float av3 = __shfl_sync(0xffffffffu, att, 24);

            // v[u=lane] = sum_r att[r] * u_r[r][lane]
            float vv = fmaf(av0, ur_s[0 * 33 + lane],
                       fmaf(av1, ur_s[1 * 33 + lane],
                       fmaf(av2, ur_s[2 * 33 + lane],
                            av3 * ur_s[3 * 33 + lane])));

            // q[b][k] = ea[r]*v[u], stored DUPLICATED: [b*128 + k][2]
            float2* qd = (float2*)q_s;
            qd[b * 128 +      lane] = make_float2(ea.x * vv, ea.x * vv);
            qd[b * 128 + 32 + lane] = make_float2(ea.y * vv, ea.y * vv);
            qd[b * 128 + 64 + lane] = make_float2(ea.z * vv, ea.z * vv);
            qd[b * 128 + 96 + lane] = make_float2(ea.w * vv, ea.w * vv);
            __syncwarp();
        }
    }

    // ================= Phase 2: out = b + q @ M via packed f32x2 FMA ==========
    // acc2[b][0] = (out_d0, out_d1), acc2[b][1] = (out_d2, out_d3), d = 4*lane..
    unsigned long long acc2[ES_PER_WARP][2];
    #pragma unroll
    for (int b = 0; b < ES_PER_WARP; ++b) {
        int es = es_base + b;
        int ent = (es < ES_TOTAL) ? __ldg(edge_index + es) : 0;
        float4 bv = ((const float4*)emb)[(long)ent * 32 + lane];
        PACKF2(acc2[b][0], bv.x, bv.y);
        PACKF2(acc2[b][1], bv.z, bv.w);
    }

    #pragma unroll 1
    for (int ru4 = 0; ru4 < 32; ++ru4) {
        // q dups for ru = 4*ru4 .. 4*ru4+3, 4 edge-sides (broadcast loads)
        ulonglong2 qa[ES_PER_WARP][2];
        #pragma unroll
        for (int b = 0; b < ES_PER_WARP; ++b) {
            qa[b][0] = *(const ulonglong2*)(q_s + (b * 128 + ru4 * 4) * 2);
            qa[b][1] = *(const ulonglong2*)(q_s + (b * 128 + ru4 * 4 + 2) * 2);
        }
        #pragma unroll
        for (int j = 0; j < 4; ++j) {
            const int ru = ru4 * 4 + j;
            ulonglong2 mv = *(const ulonglong2*)(smem + SM_M + ru * 128 + lane * 4);
            #pragma unroll
            for (int b = 0; b < ES_PER_WARP; ++b) {
                unsigned long long qq = (j & 1) ? qa[b][j >> 1].y : qa[b][j >> 1].x;
                FMA2(acc2[b][0], qq, mv.x);
                FMA2(acc2[b][1], qq, mv.y);
            }
        }
    }

    // ================= L2-normalize rows and store ============================
    #pragma unroll
    for (int b = 0; b < ES_PER_WARP; ++b) {
        int es = es_base + b;
        float v0, v1, v2, v3;
        UNPACKF2(v0, v1, acc2[b][0]);
        UNPACKF2(v2, v3, acc2[b][1]);
        float ss = v0 * v0 + v1 * v1 + v2 * v2 + v3 * v3;
        ss += __shfl_xor_sync(0xffffffffu, ss, 1);
        ss += __shfl_xor_sync(0xffffffffu, ss, 2);
        ss += __shfl_xor_sync(0xffffffffu, ss, 4);
        ss += __shfl_xor_sync(0xffffffffu, ss, 8);
        ss += __shfl_xor_sync(0xffffffffu, ss, 16);
        float norm = sqrtf(ss);
        float inv = 1.0f / fmaxf(norm, 1e-12f);
        float4 o = make_float4(v0 * inv, v1 * inv, v2 * inv, v3 * inv);
        if (es < ES_TOTAL)
            ((float4*)out)[(long)es * 32 + lane] = o;
    }
}

extern "C" void kernel_launch(void* const* d_in, const int* in_sizes, int n_in,
                              void* d_out, int out_size)
{
    (void)in_sizes; (void)n_in; (void)out_size;
    const int*   edge_index = (const int*)d_in[0];
    const float* edge_attr  = (const float*)d_in[1];
    const int*   nidx       = (const int*)d_in[2];
    const float* emb        = (const float*)d_in[3];
    const float* utab       = (const float*)d_in[4];
    const float* Wt         = (const float*)d_in[5];
    const float* wv         = (const float*)d_in[6];
    const float* Mt         = (const float*)d_in[7];
    float* out = (float*)d_out;

    cudaFuncSetAttribute(gatne_kernel,
                         cudaFuncAttributeMaxDynamicSharedMemorySize, SMEM_BYTES);
    gatne_kernel<<<NBLOCKS, THREADS, SMEM_BYTES>>>(
        edge_index, edge_attr, nidx, emb, utab, Wt, wv, Mt, out);
}

// round 7
// speedup vs baseline: 1.2052x; 1.2052x over previous
#include <cuda_runtime.h>
#include <math.h>
#include <stdint.h>

// Problem constants (GraphEmbedderGATNE): N=200000, R=4, D=128, U=32, A=16, E=131072, K=10
#define N_ENT 200000
#define R_ 4
#define D_ 128
#define U_ 32
#define A_ 16
#define E_ 131072
#define K_ 10
#define ES_TOTAL (2 * E_)                 // 262144 edge-sides
#define WPB 20                            // warps per block
#define ES_PER_WARP 8
#define THREADS (WPB * 32)                // 640
#define TILE 160                          // edge-sides per block (10 x 16-row MMA tiles)
#define NBLOCKS ((ES_TOTAL + TILE - 1) / TILE)   // 1639

#define QPAD 132                          // q tile row stride (conflict-free A frags)
#define MPAD 136                          // M tile row stride (conflict-free B frags)

// Shared-memory layout (float offsets)
#define SM_W 0                            // W transposed: [r*512 + a*32 + u], 2048
#define SM_w 2048                         // w: [r*16 + a], 64
#define SM_MT 2112                        // M (tf32-rounded): [k*136 + d], 17408
#define SM_Q (SM_MT + D_ * MPAD)          // 19520: q tile [row*132 + k], 21120 (reused as epilogue)
#define SM_SCR (SM_Q + TILE * QPAD)       // 40640: per-warp scratch
#define UR_OFF 0                          // ur: [r*33 + u], 132
#define WR_OFF 132                        // wr: [u*18 + a], 576
#define WARP_SCR 708
#define SMEM_FLOATS (SM_SCR + WPB * WARP_SCR)    // 54800
#define SMEM_BYTES (SMEM_FLOATS * 4)             // 219200 bytes

__device__ __forceinline__ float tanh_fast(float x) {
    float y;
    asm("tanh.approx.f32 %0, %1;" : "=f"(y) : "f"(x));
    return y;
}

__device__ __forceinline__ float tf32r(float x) {
    uint32_t y;
    asm("cvt.rna.tf32.f32 %0, %1;" : "=r"(y) : "f"(x));
    return __uint_as_float(y);
}

#define MMA_TF32(c0, c1, c2, c3, a0, a1, a2, a3, b0, b1)                      \
    asm volatile("mma.sync.aligned.m16n8k8.row.col.f32.tf32.tf32.f32 "        \
                 "{%0,%1,%2,%3}, {%4,%5,%6,%7}, {%8,%9}, {%0,%1,%2,%3};"      \
                 : "+f"(c0), "+f"(c1), "+f"(c2), "+f"(c3)                     \
                 : "r"(__float_as_uint(a0)), "r"(__float_as_uint(a1)),        \
                   "r"(__float_as_uint(a2)), "r"(__float_as_uint(a3)),        \
                   "r"(__float_as_uint(b0)), "r"(__float_as_uint(b1)))

__global__ void __launch_bounds__(THREADS, 1)
gatne_kernel(const int* __restrict__ edge_index,    // [2, E]
             const float* __restrict__ edge_attr,   // [E, R]
             const int* __restrict__ nidx,          // [2, E, K]
             const float* __restrict__ emb,         // [N, D]
             const float* __restrict__ utab,        // [N, R, U]
             const float* __restrict__ Wt,          // [R, U, A]
             const float* __restrict__ wv,          // [R, A]
             const float* __restrict__ Mt,          // [R, U, D]
             float* __restrict__ out)               // [2, E, D]
{
    extern __shared__ float smem[];
    const int tid = threadIdx.x;

    // --- cooperative loads: W tables + M (tf32-rounded, stride MPAD) ---
    for (int i = tid; i < D_ * D_; i += THREADS) {        // i = k*128 + d
        int k = i >> 7, d = i & 127;
        smem[SM_MT + k * MPAD + d] = tf32r(Mt[i]);
    }
    for (int i = tid; i < R_ * U_ * A_; i += THREADS) {
        int r = i >> 9, rem = i & 511, uu = rem >> 4, a = rem & 15;
        smem[SM_W + r * 512 + a * 32 + uu] = Wt[i];
    }
    if (tid < R_ * A_) smem[SM_w + tid] = wv[tid];
    __syncthreads();

    const int warp = tid >> 5, lane = tid & 31;
    float* q_s  = smem + SM_Q;
    float* ur_s = smem + SM_SCR + warp * WARP_SCR + UR_OFF;
    float* wr_s = smem + SM_SCR + warp * WARP_SCR + WR_OFF;
    const float* W_s = smem + SM_W;
    const float* w_s = smem + SM_w;

    const int es_blk = blockIdx.x * TILE;
    const int rg = lane >> 3;
    const int cg = lane & 7;
    const int a0i = 2 * cg;

    // ================= Phase 1: attention -> q (tf32-rounded) into block tile ==
    #pragma unroll 1
    for (int b = 0; b < ES_PER_WARP; ++b) {
        const int row = warp * ES_PER_WARP + b;
        const int es = es_blk + row;
        if (es < ES_TOTAL) {
            const int e = es & (E_ - 1);
            const float4 ea = ((const float4*)edge_attr)[e];

            const int* nb = nidx + (long)es * K_;
            int my_n = (lane < K_) ? __ldg(nb + lane) : 0;

            float4 au = make_float4(0.f, 0.f, 0.f, 0.f);
            #pragma unroll
            for (int k = 0; k < K_; ++k) {
                int nbr = __shfl_sync(0xffffffffu, my_n, k);
                float4 t = ((const float4*)utab)[(long)nbr * 32 + lane];
                au.x += t.x; au.y += t.y; au.z += t.z; au.w += t.w;
            }
            const float ik = 1.0f / (float)K_;
            au.x *= ik; au.y *= ik; au.z *= ik; au.w *= ik;

            const int ub = 4 * cg;
            ur_s[rg * 33 + ub + 0] = au.x;
            ur_s[rg * 33 + ub + 1] = au.y;
            ur_s[rg * 33 + ub + 2] = au.z;
            ur_s[rg * 33 + ub + 3] = au.w;

            #pragma unroll
            for (int a2 = 0; a2 < 8; ++a2) {
                int a = 2 * a2;
                float f0 = fmaf(ea.x, W_s[a * 32 + lane],
                           fmaf(ea.y, W_s[512 + a * 32 + lane],
                           fmaf(ea.z, W_s[1024 + a * 32 + lane],
                                ea.w * W_s[1536 + a * 32 + lane])));
                float f1 = fmaf(ea.x, W_s[(a + 1) * 32 + lane],
                           fmaf(ea.y, W_s[512 + (a + 1) * 32 + lane],
                           fmaf(ea.z, W_s[1024 + (a + 1) * 32 + lane],
                                ea.w * W_s[1536 + (a + 1) * 32 + lane])));
                ((float2*)(wr_s + lane * 18))[a2] = make_float2(f0, f1);
            }
            __syncwarp();

            float t0 = 0.f, t1 = 0.f;
            #pragma unroll
            for (int uu = 0; uu < U_; ++uu) {
                float urv = ur_s[rg * 33 + uu];
                float2 w2 = *(const float2*)(wr_s + uu * 18 + a0i);
                t0 = fmaf(urv, w2.x, t0);
                t1 = fmaf(urv, w2.y, t1);
            }
            float wr0 = fmaf(ea.x, w_s[a0i], fmaf(ea.y, w_s[16 + a0i],
                        fmaf(ea.z, w_s[32 + a0i], ea.w * w_s[48 + a0i])));
            float wr1 = fmaf(ea.x, w_s[a0i + 1], fmaf(ea.y, w_s[16 + a0i + 1],
                        fmaf(ea.z, w_s[32 + a0i + 1], ea.w * w_s[48 + a0i + 1])));
            float sc = tanh_fast(t0) * wr0 + tanh_fast(t1) * wr1;

            sc += __shfl_xor_sync(0xffffffffu, sc, 1);
            sc += __shfl_xor_sync(0xffffffffu, sc, 2);
            sc += __shfl_xor_sync(0xffffffffu, sc, 4);
            float mx = sc;
            mx = fmaxf(mx, __shfl_xor_sync(0xffffffffu, mx, 8));
            mx = fmaxf(mx, __shfl_xor_sync(0xffffffffu, mx, 16));
            float ex = __expf(sc - mx);
            float ssum = ex;
            ssum += __shfl_xor_sync(0xffffffffu, ssum, 8);
            ssum += __shfl_xor_sync(0xffffffffu, ssum, 16);
            float att = __fdividef(ex, ssum);
            float av0 = __shfl_sync(0xffffffffu, att, 0);
            float av1 = __shfl_sync(0xffffffffu, att, 8);
            float av2 = __shfl_sync(0xffffffffu, att, 16);
            float av3 = __shfl_sync(0xffffffffu, att, 24);

            float vv = fmaf(av0, ur_s[0 * 33 + lane],
                       fmaf(av1, ur_s[1 * 33 + lane],
                       fmaf(av2, ur_s[2 * 33 + lane],
                            av3 * ur_s[3 * 33 + lane])));

            // q[row][r*32+lane] = tf32(ea[r]*vv)
            q_s[row * QPAD +      lane] = tf32r(ea.x * vv);
            q_s[row * QPAD + 32 + lane] = tf32r(ea.y * vv);
            q_s[row * QPAD + 64 + lane] = tf32r(ea.z * vv);
            q_s[row * QPAD + 96 + lane] = tf32r(ea.w * vv);
            __syncwarp();
        }
    }
    __syncthreads();

    // ================= Phase 2: D[160x128] = q @ M via tf32 mma.sync ==========
    // warp -> (row-tile rt: 16 edges) x (d-half h: 64 cols)
    {
        const int rt = warp % 10;
        const int h  = warp / 10;
        const int gid = lane >> 2, tig = lane & 3;
        const float* Ms = smem + SM_MT;

        float c[8][4];
        #pragma unroll
        for (int nt = 0; nt < 8; ++nt)
            c[nt][0] = c[nt][1] = c[nt][2] = c[nt][3] = 0.f;

        #pragma unroll 1
        for (int ks = 0; ks < 16; ++ks) {
            const int k0 = ks * 8;
            const int ar0 = (rt * 16 + gid) * QPAD + k0 + tig;
            const int ar1 = ar0 + 8 * QPAD;
            float a0 = q_s[ar0], a1 = q_s[ar1];
            float a2 = q_s[ar0 + 4], a3 = q_s[ar1 + 4];
            #pragma unroll
            for (int nt = 0; nt < 8; ++nt) {
                const int n0 = h * 64 + nt * 8 + gid;
                float b0 = Ms[(k0 + tig) * MPAD + n0];
                float b1 = Ms[(k0 + tig + 4) * MPAD + n0];
                MMA_TF32(c[nt][0], c[nt][1], c[nt][2], c[nt][3],
                         a0, a1, a2, a3, b0, b1);
            }
        }
        __syncthreads();   // all warps done reading q tile

        // fragments -> epilogue buffer (reuse q tile)
        float* epi = smem + SM_Q;
        #pragma unroll
        for (int nt = 0; nt < 8; ++nt) {
            const int col = h * 64 + nt * 8 + 2 * tig;
            const int row0 = rt * 16 + gid;
            *(float2*)(epi + row0 * QPAD + col)       = make_float2(c[nt][0], c[nt][1]);
            *(float2*)(epi + (row0 + 8) * QPAD + col) = make_float2(c[nt][2], c[nt][3]);
        }
    }
    __syncthreads();

    // ================= Epilogue: + emb gather, l2-normalize, store ============
    {
        const float* epi = smem + SM_Q;
        int ents[8];
        #pragma unroll
        for (int i = 0; i < 8; ++i) {
            int es = es_blk + warp * 8 + i;
            ents[i] = (es < ES_TOTAL) ? __ldg(edge_index + es) : 0;
        }
        #pragma unroll 1
        for (int i = 0; i < 8; ++i) {
            const int row = warp * 8 + i;
            const int es = es_blk + row;
            float4 bv = ((const float4*)emb)[(long)ents[i] * 32 + lane];
            float4 cv = *(const float4*)(epi + row * QPAD + lane * 4);
            float v0 = cv.x + bv.x, v1 = cv.y + bv.y;
            float v2 = cv.z + bv.z, v3 = cv.w + bv.w;
            float ss = v0 * v0 + v1 * v1 + v2 * v2 + v3 * v3;
            ss += __shfl_xor_sync(0xffffffffu, ss, 1);
            ss += __shfl_xor_sync(0xffffffffu, ss, 2);
            ss += __shfl_xor_sync(0xffffffffu, ss, 4);
            ss += __shfl_xor_sync(0xffffffffu, ss, 8);
            ss += __shfl_xor_sync(0xffffffffu, ss, 16);
            float inv = 1.0f / fmaxf(sqrtf(ss), 1e-12f);
            float4 o = make_float4(v0 * inv, v1 * inv, v2 * inv, v3 * inv);
            if (es < ES_TOTAL)
                ((float4*)out)[(long)es * 32 + lane] = o;
        }
    }
}

extern "C" void kernel_launch(void* const* d_in, const int* in_sizes, int n_in,
                              void* d_out, int out_size)
{
    (void)in_sizes; (void)n_in; (void)out_size;
    const int*   edge_index = (const int*)d_in[0];
    const float* edge_attr  = (const float*)d_in[1];
    const int*   nidx       = (const int*)d_in[2];
    const float* emb        = (const float*)d_in[3];
    const float* utab       = (const float*)d_in[4];
    const float* Wt         = (const float*)d_in[5];
    const float* wv         = (const float*)d_in[6];
    const float* Mt         = (const float*)d_in[7];
    float* out = (float*)d_out;

    cudaFuncSetAttribute(gatne_kernel,
                         cudaFuncAttributeMaxDynamicSharedMemorySize, SMEM_BYTES);
    gatne_kernel<<<NBLOCKS, THREADS, SMEM_BYTES>>>(
        edge_index, edge_attr, nidx, emb, utab, Wt, wv, Mt, out);
}